// round 7
// baseline (speedup 1.0000x reference)
#include <cuda_runtime.h>
#include <cuda_bf16.h>
#include <cstdint>

#define NN 100000
#define EE 600000
#define RR 3
#define DIN 256
#define DH  128
#define NCLS 16
#define NEG_SLOPE 0.01f

#define SCAN_N (RR * NN)
#define SCAN_B 1024
#define SCAN_NB ((SCAN_N + SCAN_B - 1) / SCAN_B)

// GEMM: A resident full-K in smem; B double-buffered in KC chunks
#define KC 32
#define BSTR 40                     // B chunk smem row stride (elems) -> 80 B
#define BTILE_B (128 * BSTR * 2)    // 10240 B (one of Bh/Bl)
#define BSTAGE_B (2 * BTILE_B)      // 20480 B per stage
#define SMEM_MAX (2 * 128 * (DIN + 8) * 2 + 2 * BSTAGE_B)   // 176128 B @ K=256

__device__ __forceinline__ uint32_t smem_u32(const void* p) {
    uint32_t a;
    asm("{ .reg .u64 t; cvta.to.shared.u64 t, %1; cvt.u32.u64 %0, t; }" : "=r"(a) : "l"(p));
    return a;
}

#define LDSM4(r, a) \
    asm volatile("ldmatrix.sync.aligned.m8n8.x4.shared.b16 {%0,%1,%2,%3}, [%4];" \
        : "=r"((r)[0]), "=r"((r)[1]), "=r"((r)[2]), "=r"((r)[3]) : "r"(a))

__device__ __forceinline__ void mma16816(float* d, const uint32_t* a, const uint32_t* b) {
    asm volatile("mma.sync.aligned.m16n8k16.row.col.f32.bf16.bf16.f32 "
                 "{%0,%1,%2,%3}, {%4,%5,%6,%7}, {%8,%9}, {%0,%1,%2,%3};"
                 : "+f"(d[0]), "+f"(d[1]), "+f"(d[2]), "+f"(d[3])
                 : "r"(a[0]), "r"(a[1]), "r"(a[2]), "r"(a[3]), "r"(b[0]), "r"(b[1]));
}

// ================= scratch =================
__device__ float g_z[(size_t)RR * NN * DH];
__device__ float g_acc[(size_t)NN * DH];
__device__ __nv_bfloat16 g_xhi[(size_t)NN * DIN];
__device__ __nv_bfloat16 g_xlo[(size_t)NN * DIN];
__device__ __nv_bfloat16 g_hhi[(size_t)NN * DH];
__device__ __nv_bfloat16 g_hlo[(size_t)NN * DH];
__device__ __nv_bfloat16 g_w0hi[RR * DH * DIN];
__device__ __nv_bfloat16 g_w0lo[RR * DH * DIN];
__device__ __nv_bfloat16 g_w1hi[RR * DH * DH];
__device__ __nv_bfloat16 g_w1lo[RR * DH * DH];
__device__ float g_so[SCAN_N];
__device__ float g_si[SCAN_N];
__device__ int   g_co[SCAN_N];
__device__ int   g_ci[SCAN_N];
__device__ int   g_off[SCAN_N + 1];
__device__ int   g_cursor[SCAN_N];
__device__ int   g_bsum[SCAN_NB];
__device__ int2  g_edge[RR * EE];     // {src, float_bits(so[src]*si[dst])}

// ================= degrees + CSR =================
__global__ void deg_zero_kernel() {
    int i = blockIdx.x * blockDim.x + threadIdx.x;
    if (i < SCAN_N) { g_co[i] = 0; g_ci[i] = 0; }
}
__global__ void deg_hist_kernel(const int* __restrict__ src, const int* __restrict__ dst) {
    int i = blockIdx.x * blockDim.x + threadIdx.x;
    if (i >= RR * EE) return;
    int r = i / EE;
    atomicAdd(&g_co[r * NN + src[i]], 1);
    atomicAdd(&g_ci[r * NN + dst[i]], 1);
}
__global__ void deg_scale_kernel() {
    int i = blockIdx.x * blockDim.x + threadIdx.x;
    if (i >= SCAN_N) return;
    int co = g_co[i]; if (co < 1) co = 1;
    int ci = g_ci[i]; if (ci < 1) ci = 1;
    g_so[i] = rsqrtf((float)co);
    g_si[i] = rsqrtf((float)ci);
}
__global__ void scan1_kernel() {
    __shared__ int tmp[SCAN_B];
    int t = threadIdx.x;
    int i = blockIdx.x * SCAN_B + t;
    int v = (i < SCAN_N) ? g_ci[i] : 0;
    tmp[t] = v;
    __syncthreads();
    for (int o = 1; o < SCAN_B; o <<= 1) {
        int u = (t >= o) ? tmp[t - o] : 0;
        __syncthreads();
        tmp[t] += u;
        __syncthreads();
    }
    if (i < SCAN_N) g_off[i] = tmp[t] - v;
    if (t == SCAN_B - 1) g_bsum[blockIdx.x] = tmp[t];
}
__global__ void scan2_kernel() {
    if (threadIdx.x == 0 && blockIdx.x == 0) {
        int run = 0;
        for (int b = 0; b < SCAN_NB; b++) { int v = g_bsum[b]; g_bsum[b] = run; run += v; }
        g_off[SCAN_N] = run;
    }
}
__global__ void scan3_kernel() {
    int i = blockIdx.x * SCAN_B + threadIdx.x;
    if (i < SCAN_N) {
        int v = g_off[i] + g_bsum[blockIdx.x];
        g_off[i] = v;
        g_cursor[i] = v;
    }
}
__global__ void fill_kernel(const int* __restrict__ src, const int* __restrict__ dst) {
    int i = blockIdx.x * blockDim.x + threadIdx.x;
    if (i >= RR * EE) return;
    int r = i / EE;
    int s = src[i], d = dst[i];
    int pos = atomicAdd(&g_cursor[r * NN + d], 1);
    float coef = g_so[r * NN + s] * g_si[r * NN + d];
    g_edge[pos] = make_int2(s, __float_as_int(coef));
}

// ================= precision splits =================
__global__ void split_x_kernel(const float* __restrict__ in,
                               __nv_bfloat16* __restrict__ hi,
                               __nv_bfloat16* __restrict__ lo, size_t n4) {
    size_t i = (size_t)blockIdx.x * blockDim.x + threadIdx.x;
    if (i >= n4) return;
    float4 v = ((const float4*)in)[i];
    float vv[4] = {v.x, v.y, v.z, v.w};
    __nv_bfloat16 h[4], l[4];
#pragma unroll
    for (int q = 0; q < 4; q++) {
        h[q] = __float2bfloat16_rn(vv[q]);
        l[q] = __float2bfloat16_rn(vv[q] - __bfloat162float(h[q]));
    }
    __nv_bfloat162 hh0; hh0.x = h[0]; hh0.y = h[1];
    __nv_bfloat162 hh1; hh1.x = h[2]; hh1.y = h[3];
    __nv_bfloat162 ll0; ll0.x = l[0]; ll0.y = l[1];
    __nv_bfloat162 ll1; ll1.x = l[2]; ll1.y = l[3];
    ((__nv_bfloat162*)hi)[i * 2]     = hh0;
    ((__nv_bfloat162*)hi)[i * 2 + 1] = hh1;
    ((__nv_bfloat162*)lo)[i * 2]     = ll0;
    ((__nv_bfloat162*)lo)[i * 2 + 1] = ll1;
}

__global__ void wsplit_kernel(const float* __restrict__ W,
                              __nv_bfloat16* __restrict__ thi,
                              __nv_bfloat16* __restrict__ tlo, int K) {
    int i = blockIdx.x * blockDim.x + threadIdx.x;
    if (i >= RR * K * DH) return;
    int r = i / (K * DH);
    int rem = i - r * K * DH;
    int k = rem / DH;
    int n = rem - k * DH;
    float v = W[i];
    __nv_bfloat16 h = __float2bfloat16_rn(v);
    __nv_bfloat16 l = __float2bfloat16_rn(v - __bfloat162float(h));
    size_t o = (size_t)r * DH * K + (size_t)n * K + k;
    thi[o] = h;
    tlo[o] = l;
}

// ================= A-resident split GEMM: all 3 relations per CTA =================
// smem: [Ahi full-K | Alo full-K | B stage0 (Bh,Bl) | B stage1 (Bh,Bl)]
__global__ __launch_bounds__(512, 1)
void mma_gemm(int K,
              const __nv_bfloat16* __restrict__ Ahi, const __nv_bfloat16* __restrict__ Alo,
              const __nv_bfloat16* __restrict__ Bhi_all, const __nv_bfloat16* __restrict__ Blo_all,
              float* __restrict__ Call) {
    extern __shared__ char smem[];
    uint32_t sb = smem_u32(smem);
    int tid = threadIdx.x, wid = tid >> 5, lane = tid & 31;
    int mbase = blockIdx.x * 128;
    const int warp_m = (wid & 3) * 32;
    const int warp_n = (wid >> 2) * 32;

    const uint32_t astr = (uint32_t)(K + 8) * 2;  // A smem row bytes
    const uint32_t ATILE = 128u * astr;
    const uint32_t Bbase = sb + 2u * ATILE;

    // ---- A resident load (hi + lo, full K) ----
    {
        int nseg = K >> 3;
        int per = 128 * nseg;
        for (int i = tid; i < 2 * per; i += 512) {
            int t = i / per;
            int p = i - t * per;
            int row = p / nseg, seg = p - row * nseg;
            uint32_t sa = sb + (uint32_t)t * ATILE + (uint32_t)row * astr + (uint32_t)seg * 16;
            int grow = mbase + row;
            const __nv_bfloat16* g = (t ? Alo : Ahi) + (size_t)grow * K + seg * 8;
            int sz = (grow < NN) ? 16 : 0;
            asm volatile("cp.async.cg.shared.global [%0], [%1], 16, %2;"
                         :: "r"(sa), "l"(g), "r"(sz));
        }
        asm volatile("cp.async.commit_group;" ::: "memory");
    }

    const int nchunk = K / KC;
    const int total = RR * nchunk;

    // ---- B chunk loader: relation r, chunk c, stage st ----
    auto load_B = [&](int st, int r, int c) {
        const __nv_bfloat16* Bh = Bhi_all + (size_t)r * DH * K;
        const __nv_bfloat16* Bl = Blo_all + (size_t)r * DH * K;
        int k0 = c * KC;
#pragma unroll
        for (int i = 0; i < 2; i++) {
            int idx = tid + i * 512;          // 1024 segs of 16B
            int tile = idx >> 9;              // 0=hi 1=lo
            int p = idx & 511;
            int row = p >> 2, seg = p & 3;
            uint32_t sa = Bbase + (uint32_t)st * BSTAGE_B + (uint32_t)tile * BTILE_B
                        + (uint32_t)row * (BSTR * 2) + (uint32_t)seg * 16;
            const __nv_bfloat16* g = (tile ? Bl : Bh) + (size_t)row * K + k0 + seg * 8;
            asm volatile("cp.async.cg.shared.global [%0], [%1], 16;" :: "r"(sa), "l"(g));
        }
        asm volatile("cp.async.commit_group;" ::: "memory");
    };

    float acc[2][4][4];
#pragma unroll
    for (int mt = 0; mt < 2; mt++)
#pragma unroll
        for (int nt = 0; nt < 4; nt++)
#pragma unroll
            for (int q = 0; q < 4; q++) acc[mt][nt][q] = 0.0f;

    load_B(0, 0, 0);

    for (int cc = 0; cc < total; cc++) {
        int r = cc / nchunk;
        int c = cc - r * nchunk;
        if (cc + 1 < total) {
            int r2 = (cc + 1) / nchunk;
            load_B((cc + 1) & 1, r2, (cc + 1) - r2 * nchunk);
            asm volatile("cp.async.wait_group 1;" ::: "memory");
        } else {
            asm volatile("cp.async.wait_group 0;" ::: "memory");
        }
        __syncthreads();

        uint32_t bbase = Bbase + (uint32_t)(cc & 1) * BSTAGE_B;
#pragma unroll
        for (int ks = 0; ks < KC; ks += 16) {
            // A fragments from resident smem
            uint32_t ah[2][4], al[2][4];
            const int ar = lane & 15;
            const uint32_t acB = (uint32_t)(c * KC + ks + ((lane >> 4) << 3)) * 2;
#pragma unroll
            for (int mt = 0; mt < 2; mt++) {
                uint32_t addr = sb + (uint32_t)(warp_m + mt * 16 + ar) * astr + acB;
                LDSM4(ah[mt], addr);
                LDSM4(al[mt], addr + ATILE);
            }
            const int br = ((lane >> 4) << 3) + (lane & 7);
            const int bc = ks + (((lane >> 3) & 1) << 3);
#pragma unroll
            for (int j = 0; j < 2; j++) {
                uint32_t bh4[4], bl4[4];
                uint32_t addr = bbase + (uint32_t)(warp_n + j * 16 + br) * (BSTR * 2) + (uint32_t)bc * 2;
                LDSM4(bh4, addr);
                LDSM4(bl4, addr + BTILE_B);
#pragma unroll
                for (int mt = 0; mt < 2; mt++) {
#pragma unroll
                    for (int half = 0; half < 2; half++) {
                        float* a4 = acc[mt][j * 2 + half];
                        mma16816(a4, ah[mt], &bh4[half * 2]);
                        mma16816(a4, ah[mt], &bl4[half * 2]);
                        mma16816(a4, al[mt], &bh4[half * 2]);
                    }
                }
            }
        }
        __syncthreads();

        if (c == nchunk - 1) {
            // epilogue for relation r, then reset accumulators
            float* C = Call + (size_t)r * NN * DH;
#pragma unroll
            for (int mt = 0; mt < 2; mt++) {
                int row0 = mbase + warp_m + mt * 16 + (lane >> 2);
#pragma unroll
                for (int nt = 0; nt < 4; nt++) {
                    int col = warp_n + nt * 8 + (lane & 3) * 2;
                    if (row0 < NN)
                        *(float2*)(C + (size_t)row0 * DH + col) = make_float2(acc[mt][nt][0], acc[mt][nt][1]);
                    if (row0 + 8 < NN)
                        *(float2*)(C + (size_t)(row0 + 8) * DH + col) = make_float2(acc[mt][nt][2], acc[mt][nt][3]);
                    acc[mt][nt][0] = acc[mt][nt][1] = acc[mt][nt][2] = acc[mt][nt][3] = 0.0f;
                }
            }
        }
    }
}

// ================= gather passes (one relation per launch, L2-resident z slice) =================
// MODE 0: init  acc = biasSum + sum
// MODE 1: mid   acc += sum
// MODE 2: final layer0: v = acc + sum; leaky; -> bf16 hi/lo
// MODE 3: final layer1: v = acc + sum; -> f32 out
template <int MODE>
__global__ __launch_bounds__(256)
void gpass(const float* __restrict__ z, const int* __restrict__ off,
           const float* __restrict__ bias, float* __restrict__ acc,
           __nv_bfloat16* __restrict__ outhi, __nv_bfloat16* __restrict__ outlo,
           float* __restrict__ outf) {
    int w = blockIdx.x * 8 + (threadIdx.x >> 5);
    if (w >= NN) return;
    int lane = threadIdx.x & 31;
    int c0 = lane * 4;

    float a4[4];
    if (MODE == 0) {
#pragma unroll
        for (int j = 0; j < 4; j++)
            a4[j] = bias[c0 + j] + bias[DH + c0 + j] + bias[2 * DH + c0 + j];
    } else {
        float4 t = *(const float4*)(acc + (size_t)w * DH + c0);
        a4[0] = t.x; a4[1] = t.y; a4[2] = t.z; a4[3] = t.w;
    }

    int beg = off[w];
    int end = off[w + 1];
#pragma unroll 2
    for (int e = beg; e < end; e++) {
        int2 ec = __ldg(&g_edge[e]);
        float coef = __int_as_float(ec.y);
        float4 v = *(const float4*)(z + (size_t)ec.x * DH + c0);
        a4[0] = fmaf(coef, v.x, a4[0]);
        a4[1] = fmaf(coef, v.y, a4[1]);
        a4[2] = fmaf(coef, v.z, a4[2]);
        a4[3] = fmaf(coef, v.w, a4[3]);
    }

    if (MODE <= 1) {
        *(float4*)(acc + (size_t)w * DH + c0) = make_float4(a4[0], a4[1], a4[2], a4[3]);
    } else if (MODE == 2) {
#pragma unroll
        for (int j = 0; j < 4; j++)
            a4[j] = (a4[j] > 0.f) ? a4[j] : NEG_SLOPE * a4[j];
        __nv_bfloat16 h[4], l[4];
#pragma unroll
        for (int j = 0; j < 4; j++) {
            h[j] = __float2bfloat16_rn(a4[j]);
            l[j] = __float2bfloat16_rn(a4[j] - __bfloat162float(h[j]));
        }
        __nv_bfloat162 hh0; hh0.x = h[0]; hh0.y = h[1];
        __nv_bfloat162 hh1; hh1.x = h[2]; hh1.y = h[3];
        __nv_bfloat162 ll0; ll0.x = l[0]; ll0.y = l[1];
        __nv_bfloat162 ll1; ll1.x = l[2]; ll1.y = l[3];
        __nv_bfloat162* oh = (__nv_bfloat162*)(outhi + (size_t)w * DH + c0);
        __nv_bfloat162* ol = (__nv_bfloat162*)(outlo + (size_t)w * DH + c0);
        oh[0] = hh0; oh[1] = hh1;
        ol[0] = ll0; ol[1] = ll1;
    } else {
        *(float4*)(outf + (size_t)w * DH + c0) = make_float4(a4[0], a4[1], a4[2], a4[3]);
    }
}

// ================= logits =================
__global__ __launch_bounds__(256)
void logits_kernel(const float* __restrict__ h2, const float* __restrict__ fcW,
                   const float* __restrict__ fcb, float* __restrict__ out) {
    __shared__ float Ws[DH * NCLS];
    __shared__ float bs[NCLS];
    int tid = threadIdx.x;
    for (int i = tid; i < DH * NCLS; i += 256) Ws[i] = fcW[i];
    if (tid < NCLS) bs[tid] = fcb[tid];
    __syncthreads();

    int n = blockIdx.x * 256 + tid;
    if (n >= NN) return;
    const float4* row = (const float4*)(h2 + (size_t)n * DH);
    float acc[NCLS];
#pragma unroll
    for (int c = 0; c < NCLS; c++) acc[c] = bs[c];
    for (int k4 = 0; k4 < DH / 4; k4++) {
        float4 hv = row[k4];
        float hs[4] = {hv.x, hv.y, hv.z, hv.w};
#pragma unroll
        for (int u = 0; u < 4; u++) {
            int k = k4 * 4 + u;
#pragma unroll
            for (int c = 0; c < NCLS; c++) acc[c] = fmaf(hs[u], Ws[k * NCLS + c], acc[c]);
        }
    }
    float* o = out + (size_t)n * NCLS;
#pragma unroll
    for (int c = 0; c < NCLS; c++) o[c] = acc[c];
}

// ================= launch =================
extern "C" void kernel_launch(void* const* d_in, const int* in_sizes, int n_in,
                              void* d_out, int out_size) {
    const float* x   = (const float*)d_in[0];
    const int*   src = (const int*)  d_in[1];
    const int*   dst = (const int*)  d_in[2];
    const float* W0  = (const float*)d_in[3];
    const float* b0  = (const float*)d_in[4];
    const float* W1  = (const float*)d_in[5];
    const float* b1  = (const float*)d_in[6];
    const float* fcW = (const float*)d_in[7];
    const float* fcb = (const float*)d_in[8];

    float* out    = (float*)d_out;
    float* h2     = out;
    float* logits = out + (size_t)NN * DH;

    const int T = 256;

    float* zbuf;   cudaGetSymbolAddress((void**)&zbuf, g_z);
    float* accb;   cudaGetSymbolAddress((void**)&accb, g_acc);
    int*   offp;   cudaGetSymbolAddress((void**)&offp, g_off);
    __nv_bfloat16 *xhi, *xlo, *hhi, *hlo, *w0hi, *w0lo, *w1hi, *w1lo;
    cudaGetSymbolAddress((void**)&xhi, g_xhi);
    cudaGetSymbolAddress((void**)&xlo, g_xlo);
    cudaGetSymbolAddress((void**)&hhi, g_hhi);
    cudaGetSymbolAddress((void**)&hlo, g_hlo);
    cudaGetSymbolAddress((void**)&w0hi, g_w0hi);
    cudaGetSymbolAddress((void**)&w0lo, g_w0lo);
    cudaGetSymbolAddress((void**)&w1hi, g_w1hi);
    cudaGetSymbolAddress((void**)&w1lo, g_w1lo);

    cudaFuncSetAttribute(mma_gemm, cudaFuncAttributeMaxDynamicSharedMemorySize, SMEM_MAX);

    const int gemmBlocks = (NN + 127) / 128;
    const int gatherGrid = (NN + 7) / 8;
    const uint32_t smem0 = 2u * 128u * (DIN + 8) * 2 + 2 * BSTAGE_B;  // K=256
    const uint32_t smem1 = 2u * 128u * (DH + 8) * 2 + 2 * BSTAGE_B;   // K=128

    // (0..2) splits, (3) layer-0 GEMM  -> ncu captures launch index 3
    size_t xn4 = (size_t)NN * DIN / 4;
    split_x_kernel<<<(int)((xn4 + T - 1) / T), T>>>(x, xhi, xlo, xn4);
    wsplit_kernel<<<(RR * DIN * DH + T - 1) / T, T>>>(W0, w0hi, w0lo, DIN);
    wsplit_kernel<<<(RR * DH * DH + T - 1) / T, T>>>(W1, w1hi, w1lo, DH);
    mma_gemm<<<gemmBlocks, 512, smem0>>>(DIN, xhi, xlo, w0hi, w0lo, zbuf);

    // degrees + CSR
    deg_zero_kernel<<<(SCAN_N + T - 1) / T, T>>>();
    deg_hist_kernel<<<(RR * EE + T - 1) / T, T>>>(src, dst);
    deg_scale_kernel<<<(SCAN_N + T - 1) / T, T>>>();
    scan1_kernel<<<SCAN_NB, SCAN_B>>>();
    scan2_kernel<<<1, 32>>>();
    scan3_kernel<<<SCAN_NB, SCAN_B>>>();
    fill_kernel<<<(RR * EE + T - 1) / T, T>>>(src, dst);

    // layer 0 gather: per-relation passes
    gpass<0><<<gatherGrid, T>>>(zbuf + 0 * (size_t)NN * DH, offp + 0 * NN, b0, accb, nullptr, nullptr, nullptr);
    gpass<1><<<gatherGrid, T>>>(zbuf + 1 * (size_t)NN * DH, offp + 1 * NN, b0, accb, nullptr, nullptr, nullptr);
    gpass<2><<<gatherGrid, T>>>(zbuf + 2 * (size_t)NN * DH, offp + 2 * NN, b0, accb, hhi, hlo, nullptr);

    // layer 1
    mma_gemm<<<gemmBlocks, 512, smem1>>>(DH, hhi, hlo, w1hi, w1lo, zbuf);
    gpass<0><<<gatherGrid, T>>>(zbuf + 0 * (size_t)NN * DH, offp + 0 * NN, b1, accb, nullptr, nullptr, nullptr);
    gpass<1><<<gatherGrid, T>>>(zbuf + 1 * (size_t)NN * DH, offp + 1 * NN, b1, accb, nullptr, nullptr, nullptr);
    gpass<3><<<gatherGrid, T>>>(zbuf + 2 * (size_t)NN * DH, offp + 2 * NN, b1, accb, nullptr, nullptr, h2);

    // fc head
    logits_kernel<<<(NN + T - 1) / T, T>>>(h2, fcW, fcb, logits);
}

// round 8
// speedup vs baseline: 1.2420x; 1.2420x over previous
#include <cuda_runtime.h>
#include <cuda_bf16.h>
#include <cstdint>

#define NN 100000
#define EE 600000
#define RR 3
#define DIN 256
#define DH  128
#define NCLS 16
#define NEG_SLOPE 0.01f

#define SCAN_N (RR * NN)
#define SCAN_B 1024
#define SCAN_NB ((SCAN_N + SCAN_B - 1) / SCAN_B)

// GEMM tiling: A and B double-buffered in KC chunks (R6 scheme, 2 CTAs/SM)
#define KC 32
#define ASTR 40                    // padded smem row length (elems) -> 80B
#define TILE_B (128 * ASTR * 2)    // 10240 B per tile
#define STAGE_B (4 * TILE_B)       // Ah, Al, Bh, Bl
#define GS_TOTAL (2 * STAGE_B)     // 81920 B double-buffered

__device__ __forceinline__ uint32_t smem_u32(const void* p) {
    uint32_t a;
    asm("{ .reg .u64 t; cvta.to.shared.u64 t, %1; cvt.u32.u64 %0, t; }" : "=r"(a) : "l"(p));
    return a;
}

#define LDSM4(r, a) \
    asm volatile("ldmatrix.sync.aligned.m8n8.x4.shared.b16 {%0,%1,%2,%3}, [%4];" \
        : "=r"((r)[0]), "=r"((r)[1]), "=r"((r)[2]), "=r"((r)[3]) : "r"(a))

__device__ __forceinline__ void mma16816(float* d, const uint32_t* a, const uint32_t* b) {
    asm volatile("mma.sync.aligned.m16n8k16.row.col.f32.bf16.bf16.f32 "
                 "{%0,%1,%2,%3}, {%4,%5,%6,%7}, {%8,%9}, {%0,%1,%2,%3};"
                 : "+f"(d[0]), "+f"(d[1]), "+f"(d[2]), "+f"(d[3])
                 : "r"(a[0]), "r"(a[1]), "r"(a[2]), "r"(a[3]), "r"(b[0]), "r"(b[1]));
}

// ================= scratch =================
__device__ float g_z[(size_t)RR * NN * DH];
__device__ __nv_bfloat16 g_xhi[(size_t)NN * DIN];
__device__ __nv_bfloat16 g_xlo[(size_t)NN * DIN];
__device__ __nv_bfloat16 g_hhi[(size_t)NN * DH];
__device__ __nv_bfloat16 g_hlo[(size_t)NN * DH];
__device__ __nv_bfloat16 g_w0hi[RR * DH * DIN];
__device__ __nv_bfloat16 g_w0lo[RR * DH * DIN];
__device__ __nv_bfloat16 g_w1hi[RR * DH * DH];
__device__ __nv_bfloat16 g_w1lo[RR * DH * DH];
__device__ float g_so[SCAN_N];
__device__ float g_si[SCAN_N];
__device__ int   g_co[SCAN_N];
__device__ int   g_ci[SCAN_N];
__device__ int   g_off[SCAN_N + 1];
__device__ int   g_cursor[SCAN_N];
__device__ int   g_bsum[SCAN_NB];
__device__ int2  g_edge[RR * EE];     // {src, float_bits(so[src]*si[dst])}

// ================= degrees + CSR =================
__global__ void deg_zero_kernel() {
    int i = blockIdx.x * blockDim.x + threadIdx.x;
    if (i < SCAN_N) { g_co[i] = 0; g_ci[i] = 0; }
}
__global__ void deg_hist_kernel(const int* __restrict__ src, const int* __restrict__ dst) {
    int i = blockIdx.x * blockDim.x + threadIdx.x;
    if (i >= RR * EE) return;
    int r = i / EE;
    atomicAdd(&g_co[r * NN + src[i]], 1);
    atomicAdd(&g_ci[r * NN + dst[i]], 1);
}
__global__ void deg_scale_kernel() {
    int i = blockIdx.x * blockDim.x + threadIdx.x;
    if (i >= SCAN_N) return;
    int co = g_co[i]; if (co < 1) co = 1;
    int ci = g_ci[i]; if (ci < 1) ci = 1;
    g_so[i] = rsqrtf((float)co);
    g_si[i] = rsqrtf((float)ci);
}
__global__ void scan1_kernel() {
    __shared__ int tmp[SCAN_B];
    int t = threadIdx.x;
    int i = blockIdx.x * SCAN_B + t;
    int v = (i < SCAN_N) ? g_ci[i] : 0;
    tmp[t] = v;
    __syncthreads();
    for (int o = 1; o < SCAN_B; o <<= 1) {
        int u = (t >= o) ? tmp[t - o] : 0;
        __syncthreads();
        tmp[t] += u;
        __syncthreads();
    }
    if (i < SCAN_N) g_off[i] = tmp[t] - v;
    if (t == SCAN_B - 1) g_bsum[blockIdx.x] = tmp[t];
}
__global__ void scan2_kernel() {
    if (threadIdx.x == 0 && blockIdx.x == 0) {
        int run = 0;
        for (int b = 0; b < SCAN_NB; b++) { int v = g_bsum[b]; g_bsum[b] = run; run += v; }
        g_off[SCAN_N] = run;
    }
}
__global__ void scan3_kernel() {
    int i = blockIdx.x * SCAN_B + threadIdx.x;
    if (i < SCAN_N) {
        int v = g_off[i] + g_bsum[blockIdx.x];
        g_off[i] = v;
        g_cursor[i] = v;
    }
}
__global__ void fill_kernel(const int* __restrict__ src, const int* __restrict__ dst) {
    int i = blockIdx.x * blockDim.x + threadIdx.x;
    if (i >= RR * EE) return;
    int r = i / EE;
    int s = src[i], d = dst[i];
    int pos = atomicAdd(&g_cursor[r * NN + d], 1);
    float coef = g_so[r * NN + s] * g_si[r * NN + d];
    g_edge[pos] = make_int2(s, __float_as_int(coef));
}

// ================= precision splits =================
__global__ void split_x_kernel(const float* __restrict__ in,
                               __nv_bfloat16* __restrict__ hi,
                               __nv_bfloat16* __restrict__ lo, size_t n4) {
    size_t i = (size_t)blockIdx.x * blockDim.x + threadIdx.x;
    if (i >= n4) return;
    float4 v = ((const float4*)in)[i];
    float vv[4] = {v.x, v.y, v.z, v.w};
    __nv_bfloat16 h[4], l[4];
#pragma unroll
    for (int q = 0; q < 4; q++) {
        h[q] = __float2bfloat16_rn(vv[q]);
        l[q] = __float2bfloat16_rn(vv[q] - __bfloat162float(h[q]));
    }
    __nv_bfloat162 hh0; hh0.x = h[0]; hh0.y = h[1];
    __nv_bfloat162 hh1; hh1.x = h[2]; hh1.y = h[3];
    __nv_bfloat162 ll0; ll0.x = l[0]; ll0.y = l[1];
    __nv_bfloat162 ll1; ll1.x = l[2]; ll1.y = l[3];
    ((__nv_bfloat162*)hi)[i * 2]     = hh0;
    ((__nv_bfloat162*)hi)[i * 2 + 1] = hh1;
    ((__nv_bfloat162*)lo)[i * 2]     = ll0;
    ((__nv_bfloat162*)lo)[i * 2 + 1] = ll1;
}

__global__ void wsplit_kernel(const float* __restrict__ W,
                              __nv_bfloat16* __restrict__ thi,
                              __nv_bfloat16* __restrict__ tlo, int K) {
    int i = blockIdx.x * blockDim.x + threadIdx.x;
    if (i >= RR * K * DH) return;
    int r = i / (K * DH);
    int rem = i - r * K * DH;
    int k = rem / DH;
    int n = rem - k * DH;
    float v = W[i];
    __nv_bfloat16 h = __float2bfloat16_rn(v);
    __nv_bfloat16 l = __float2bfloat16_rn(v - __bfloat162float(h));
    size_t o = (size_t)r * DH * K + (size_t)n * K + k;
    thi[o] = h;
    tlo[o] = l;
}

// ================= mma.sync bf16 split GEMM (2 CTAs/SM) =================
// grid: (RR, mblocks) — relation is the FAST grid dim so the 3 CTAs sharing an
// A tile are adjacent in schedule order and hit A in L2.
__device__ __forceinline__ void load_stage(uint32_t sb, int st, int c, int K, int mbase,
                                           const __nv_bfloat16* __restrict__ Ahi,
                                           const __nv_bfloat16* __restrict__ Alo,
                                           const __nv_bfloat16* __restrict__ Bh,
                                           const __nv_bfloat16* __restrict__ Bl, int tid) {
    int k0 = c * KC;
    uint32_t sbase = sb + st * STAGE_B;
#pragma unroll
    for (int i = 0; i < 8; i++) {
        int idx = tid + i * 256;
        int tile = idx >> 9;
        int p = idx & 511;
        int row = p >> 2, seg = p & 3;
        uint32_t sa = sbase + tile * TILE_B + row * (ASTR * 2) + seg * 16;
        const __nv_bfloat16* gsrc;
        int sz = 16;
        if (tile < 2) {
            int grow = mbase + row;
            const __nv_bfloat16* base = (tile == 0) ? Ahi : Alo;
            gsrc = base + (size_t)grow * K + k0 + seg * 8;
            if (grow >= NN) sz = 0;
        } else {
            const __nv_bfloat16* base = (tile == 2) ? Bh : Bl;
            gsrc = base + (size_t)row * K + k0 + seg * 8;
        }
        asm volatile("cp.async.cg.shared.global [%0], [%1], 16, %2;"
                     :: "r"(sa), "l"(gsrc), "r"(sz));
    }
    asm volatile("cp.async.commit_group;" ::: "memory");
}

__global__ __launch_bounds__(256, 2)
void mma_gemm(int K,
              const __nv_bfloat16* __restrict__ Ahi, const __nv_bfloat16* __restrict__ Alo,
              const __nv_bfloat16* __restrict__ Bhi_all, const __nv_bfloat16* __restrict__ Blo_all,
              float* __restrict__ Call) {
    extern __shared__ char smem[];
    uint32_t sb = smem_u32(smem);
    int tid = threadIdx.x, wid = tid >> 5, lane = tid & 31;
    int r = blockIdx.x;                  // fast dim: relation
    int mbase = blockIdx.y * 128;        // slow dim: m-block
    const __nv_bfloat16* Bh = Bhi_all + (size_t)r * DH * K;
    const __nv_bfloat16* Bl = Blo_all + (size_t)r * DH * K;
    float* C = Call + (size_t)r * NN * DH;
    const int warp_m = (wid & 3) * 32;
    const int warp_n = (wid >> 2) * 64;

    float acc[2][8][4];
#pragma unroll
    for (int mt = 0; mt < 2; mt++)
#pragma unroll
        for (int nt = 0; nt < 8; nt++)
#pragma unroll
            for (int q = 0; q < 4; q++) acc[mt][nt][q] = 0.0f;

    const int nchunk = K / KC;
    load_stage(sb, 0, 0, K, mbase, Ahi, Alo, Bh, Bl, tid);

    for (int c = 0; c < nchunk; c++) {
        if (c + 1 < nchunk) {
            load_stage(sb, (c + 1) & 1, c + 1, K, mbase, Ahi, Alo, Bh, Bl, tid);
            asm volatile("cp.async.wait_group 1;" ::: "memory");
        } else {
            asm volatile("cp.async.wait_group 0;" ::: "memory");
        }
        __syncthreads();

        uint32_t base = sb + (c & 1) * STAGE_B;
#pragma unroll
        for (int ks = 0; ks < KC; ks += 16) {
            // A fragments (hi+lo) for both m-subtiles: 16 regs live
            uint32_t ah[2][4], al[2][4];
            const int ar = lane & 15;
            const int ac = ks + ((lane >> 4) << 3);
#pragma unroll
            for (int mt = 0; mt < 2; mt++) {
                uint32_t addr = base + ((warp_m + mt * 16 + ar) * ASTR + ac) * 2;
                LDSM4(ah[mt], addr);
                LDSM4(al[mt], addr + TILE_B);
            }
            // B fragments loaded per 16-column group and consumed immediately
            const int br = ((lane >> 4) << 3) + (lane & 7);
            const int bc = ks + (((lane >> 3) & 1) << 3);
#pragma unroll
            for (int j = 0; j < 4; j++) {
                uint32_t bh4[4], bl4[4];
                uint32_t addr = base + 2 * TILE_B + ((warp_n + j * 16 + br) * ASTR + bc) * 2;
                LDSM4(bh4, addr);
                LDSM4(bl4, addr + TILE_B);
#pragma unroll
                for (int mt = 0; mt < 2; mt++) {
#pragma unroll
                    for (int half = 0; half < 2; half++) {
                        float* a4 = acc[mt][j * 2 + half];
                        mma16816(a4, ah[mt], &bh4[half * 2]);
                        mma16816(a4, ah[mt], &bl4[half * 2]);
                        mma16816(a4, al[mt], &bh4[half * 2]);
                    }
                }
            }
        }
        __syncthreads();
    }

    // epilogue
#pragma unroll
    for (int mt = 0; mt < 2; mt++) {
        int row0 = mbase + warp_m + mt * 16 + (lane >> 2);
#pragma unroll
        for (int nt = 0; nt < 8; nt++) {
            int col = warp_n + nt * 8 + (lane & 3) * 2;
            if (row0 < NN)
                *(float2*)(C + (size_t)row0 * DH + col) = make_float2(acc[mt][nt][0], acc[mt][nt][1]);
            if (row0 + 8 < NN)
                *(float2*)(C + (size_t)(row0 + 8) * DH + col) = make_float2(acc[mt][nt][2], acc[mt][nt][3]);
        }
    }
}

// ================= gather: warp per dst node =================
template <int MODE>
__global__ __launch_bounds__(256)
void gather_kernel(const float* __restrict__ z, const float* __restrict__ bias,
                   float* __restrict__ outf,
                   __nv_bfloat16* __restrict__ outhi, __nv_bfloat16* __restrict__ outlo) {
    int w = blockIdx.x * 8 + (threadIdx.x >> 5);
    if (w >= NN) return;
    int lane = threadIdx.x & 31;
    int c0 = lane * 4;

    float accT[4];
#pragma unroll
    for (int j = 0; j < 4; j++)
        accT[j] = bias[c0 + j] + bias[DH + c0 + j] + bias[2 * DH + c0 + j];

#pragma unroll
    for (int r = 0; r < RR; r++) {
        int idx = r * NN + w;
        int beg = g_off[idx];
        int end = g_off[idx + 1];
        const float* zr = z + (size_t)r * NN * DH;
#pragma unroll 2
        for (int e = beg; e < end; e++) {
            int2 ec = __ldg(&g_edge[e]);
            float coef = __int_as_float(ec.y);
            float4 v = *(const float4*)(zr + (size_t)ec.x * DH + c0);
            accT[0] = fmaf(coef, v.x, accT[0]);
            accT[1] = fmaf(coef, v.y, accT[1]);
            accT[2] = fmaf(coef, v.z, accT[2]);
            accT[3] = fmaf(coef, v.w, accT[3]);
        }
    }

    if (MODE == 0) {
#pragma unroll
        for (int j = 0; j < 4; j++)
            accT[j] = (accT[j] > 0.f) ? accT[j] : NEG_SLOPE * accT[j];
        __nv_bfloat16 h[4], l[4];
#pragma unroll
        for (int j = 0; j < 4; j++) {
            h[j] = __float2bfloat16_rn(accT[j]);
            l[j] = __float2bfloat16_rn(accT[j] - __bfloat162float(h[j]));
        }
        __nv_bfloat162 hh0; hh0.x = h[0]; hh0.y = h[1];
        __nv_bfloat162 hh1; hh1.x = h[2]; hh1.y = h[3];
        __nv_bfloat162 ll0; ll0.x = l[0]; ll0.y = l[1];
        __nv_bfloat162 ll1; ll1.x = l[2]; ll1.y = l[3];
        __nv_bfloat162* oh = (__nv_bfloat162*)(outhi + (size_t)w * DH + c0);
        __nv_bfloat162* ol = (__nv_bfloat162*)(outlo + (size_t)w * DH + c0);
        oh[0] = hh0; oh[1] = hh1;
        ol[0] = ll0; ol[1] = ll1;
    } else {
        *(float4*)(outf + (size_t)w * DH + c0) = make_float4(accT[0], accT[1], accT[2], accT[3]);
    }
}

// ================= logits =================
__global__ __launch_bounds__(256)
void logits_kernel(const float* __restrict__ h2, const float* __restrict__ fcW,
                   const float* __restrict__ fcb, float* __restrict__ out) {
    __shared__ float Ws[DH * NCLS];
    __shared__ float bs[NCLS];
    int tid = threadIdx.x;
    for (int i = tid; i < DH * NCLS; i += 256) Ws[i] = fcW[i];
    if (tid < NCLS) bs[tid] = fcb[tid];
    __syncthreads();

    int n = blockIdx.x * 256 + tid;
    if (n >= NN) return;
    const float4* row = (const float4*)(h2 + (size_t)n * DH);
    float acc[NCLS];
#pragma unroll
    for (int c = 0; c < NCLS; c++) acc[c] = bs[c];
    for (int k4 = 0; k4 < DH / 4; k4++) {
        float4 hv = row[k4];
        float hs[4] = {hv.x, hv.y, hv.z, hv.w};
#pragma unroll
        for (int u = 0; u < 4; u++) {
            int k = k4 * 4 + u;
#pragma unroll
            for (int c = 0; c < NCLS; c++) acc[c] = fmaf(hs[u], Ws[k * NCLS + c], acc[c]);
        }
    }
    float* o = out + (size_t)n * NCLS;
#pragma unroll
    for (int c = 0; c < NCLS; c++) o[c] = acc[c];
}

// ================= launch =================
extern "C" void kernel_launch(void* const* d_in, const int* in_sizes, int n_in,
                              void* d_out, int out_size) {
    const float* x   = (const float*)d_in[0];
    const int*   src = (const int*)  d_in[1];
    const int*   dst = (const int*)  d_in[2];
    const float* W0  = (const float*)d_in[3];
    const float* b0  = (const float*)d_in[4];
    const float* W1  = (const float*)d_in[5];
    const float* b1  = (const float*)d_in[6];
    const float* fcW = (const float*)d_in[7];
    const float* fcb = (const float*)d_in[8];

    float* out    = (float*)d_out;
    float* h2     = out;
    float* logits = out + (size_t)NN * DH;

    const int T = 256;

    float* zbuf;   cudaGetSymbolAddress((void**)&zbuf, g_z);
    __nv_bfloat16 *xhi, *xlo, *hhi, *hlo, *w0hi, *w0lo, *w1hi, *w1lo;
    cudaGetSymbolAddress((void**)&xhi, g_xhi);
    cudaGetSymbolAddress((void**)&xlo, g_xlo);
    cudaGetSymbolAddress((void**)&hhi, g_hhi);
    cudaGetSymbolAddress((void**)&hlo, g_hlo);
    cudaGetSymbolAddress((void**)&w0hi, g_w0hi);
    cudaGetSymbolAddress((void**)&w0lo, g_w0lo);
    cudaGetSymbolAddress((void**)&w1hi, g_w1hi);
    cudaGetSymbolAddress((void**)&w1lo, g_w1lo);

    cudaFuncSetAttribute(mma_gemm, cudaFuncAttributeMaxDynamicSharedMemorySize, GS_TOTAL);

    const int gemmBlocks = (NN + 127) / 128;
    const int gatherGrid = (NN + 7) / 8;

    // (0..2) splits, (3) layer-0 GEMM  -> ncu captures launch index 3
    size_t xn4 = (size_t)NN * DIN / 4;
    split_x_kernel<<<(int)((xn4 + T - 1) / T), T>>>(x, xhi, xlo, xn4);
    wsplit_kernel<<<(RR * DIN * DH + T - 1) / T, T>>>(W0, w0hi, w0lo, DIN);
    wsplit_kernel<<<(RR * DH * DH + T - 1) / T, T>>>(W1, w1hi, w1lo, DH);
    mma_gemm<<<dim3(RR, gemmBlocks), T, GS_TOTAL>>>(DIN, xhi, xlo, w0hi, w0lo, zbuf);

    // degrees + CSR (independent of GEMM; needed before gather)
    deg_zero_kernel<<<(SCAN_N + T - 1) / T, T>>>();
    deg_hist_kernel<<<(RR * EE + T - 1) / T, T>>>(src, dst);
    deg_scale_kernel<<<(SCAN_N + T - 1) / T, T>>>();
    scan1_kernel<<<SCAN_NB, SCAN_B>>>();
    scan2_kernel<<<1, 32>>>();
    scan3_kernel<<<SCAN_NB, SCAN_B>>>();
    fill_kernel<<<(RR * EE + T - 1) / T, T>>>(src, dst);

    // layer 0 gather -> h (bf16 split)
    gather_kernel<0><<<gatherGrid, T>>>(zbuf, b0, nullptr, hhi, hlo);

    // layer 1
    mma_gemm<<<dim3(RR, gemmBlocks), T, GS_TOTAL>>>(DH, hhi, hlo, w1hi, w1lo, zbuf);
    gather_kernel<1><<<gatherGrid, T>>>(zbuf, b1, h2, nullptr, nullptr);

    // fc head
    logits_kernel<<<(NN + T - 1) / T, T>>>(h2, fcW, fcb, logits);
}

// round 9
// speedup vs baseline: 1.4198x; 1.1432x over previous
#include <cuda_runtime.h>
#include <cuda_bf16.h>
#include <cuda_fp16.h>
#include <cstdint>

#define NN 100000
#define EE 600000
#define RR 3
#define DIN 256
#define DH  128
#define NCLS 16
#define NEG_SLOPE 0.01f

#define SCAN_N (RR * NN)
#define SCAN_B 1024
#define SCAN_NB ((SCAN_N + SCAN_B - 1) / SCAN_B)

// GEMM tiling (R8 scheme, 2 CTAs/SM)
#define KC 32
#define ASTR 40
#define TILE_B (128 * ASTR * 2)
#define STAGE_B (4 * TILE_B)
#define GS_TOTAL (2 * STAGE_B)

__device__ __forceinline__ uint32_t smem_u32(const void* p) {
    uint32_t a;
    asm("{ .reg .u64 t; cvta.to.shared.u64 t, %1; cvt.u32.u64 %0, t; }" : "=r"(a) : "l"(p));
    return a;
}

#define LDSM4(r, a) \
    asm volatile("ldmatrix.sync.aligned.m8n8.x4.shared.b16 {%0,%1,%2,%3}, [%4];" \
        : "=r"((r)[0]), "=r"((r)[1]), "=r"((r)[2]), "=r"((r)[3]) : "r"(a))

__device__ __forceinline__ void mma16816(float* d, const uint32_t* a, const uint32_t* b) {
    asm volatile("mma.sync.aligned.m16n8k16.row.col.f32.bf16.bf16.f32 "
                 "{%0,%1,%2,%3}, {%4,%5,%6,%7}, {%8,%9}, {%0,%1,%2,%3};"
                 : "+f"(d[0]), "+f"(d[1]), "+f"(d[2]), "+f"(d[3])
                 : "r"(a[0]), "r"(a[1]), "r"(a[2]), "r"(a[3]), "r"(b[0]), "r"(b[1]));
}

// ================= scratch =================
__device__ __half g_z[(size_t)RR * NN * DH];          // fp16 z: 77 MB, fits L2
__device__ __nv_bfloat16 g_xhi[(size_t)NN * DIN];
__device__ __nv_bfloat16 g_xlo[(size_t)NN * DIN];
__device__ __nv_bfloat16 g_hhi[(size_t)NN * DH];
__device__ __nv_bfloat16 g_hlo[(size_t)NN * DH];
__device__ __nv_bfloat16 g_w0hi[RR * DH * DIN];
__device__ __nv_bfloat16 g_w0lo[RR * DH * DIN];
__device__ __nv_bfloat16 g_w1hi[RR * DH * DH];
__device__ __nv_bfloat16 g_w1lo[RR * DH * DH];
__device__ float g_so[SCAN_N];
__device__ float g_si[SCAN_N];
__device__ int   g_co[SCAN_N];
__device__ int   g_ci[SCAN_N];
__device__ int   g_off[SCAN_N + 1];
__device__ int   g_cursor[SCAN_N];
__device__ int   g_bsum[SCAN_NB];
__device__ int2  g_edge[RR * EE];     // {src, float_bits(so[src]*si[dst])}

// ================= degrees + CSR =================
__global__ void deg_zero_kernel() {
    int i = blockIdx.x * blockDim.x + threadIdx.x;
    if (i < SCAN_N) { g_co[i] = 0; g_ci[i] = 0; }
}
__global__ void deg_hist_kernel(const int* __restrict__ src, const int* __restrict__ dst) {
    int i = blockIdx.x * blockDim.x + threadIdx.x;
    if (i >= RR * EE) return;
    int r = i / EE;
    atomicAdd(&g_co[r * NN + src[i]], 1);
    atomicAdd(&g_ci[r * NN + dst[i]], 1);
}
__global__ void deg_scale_kernel() {
    int i = blockIdx.x * blockDim.x + threadIdx.x;
    if (i >= SCAN_N) return;
    int co = g_co[i]; if (co < 1) co = 1;
    int ci = g_ci[i]; if (ci < 1) ci = 1;
    g_so[i] = rsqrtf((float)co);
    g_si[i] = rsqrtf((float)ci);
}
__global__ void scan1_kernel() {
    __shared__ int tmp[SCAN_B];
    int t = threadIdx.x;
    int i = blockIdx.x * SCAN_B + t;
    int v = (i < SCAN_N) ? g_ci[i] : 0;
    tmp[t] = v;
    __syncthreads();
    for (int o = 1; o < SCAN_B; o <<= 1) {
        int u = (t >= o) ? tmp[t - o] : 0;
        __syncthreads();
        tmp[t] += u;
        __syncthreads();
    }
    if (i < SCAN_N) g_off[i] = tmp[t] - v;
    if (t == SCAN_B - 1) g_bsum[blockIdx.x] = tmp[t];
}
__global__ void scan2_kernel() {
    if (threadIdx.x == 0 && blockIdx.x == 0) {
        int run = 0;
        for (int b = 0; b < SCAN_NB; b++) { int v = g_bsum[b]; g_bsum[b] = run; run += v; }
        g_off[SCAN_N] = run;
    }
}
__global__ void scan3_kernel() {
    int i = blockIdx.x * SCAN_B + threadIdx.x;
    if (i < SCAN_N) {
        int v = g_off[i] + g_bsum[blockIdx.x];
        g_off[i] = v;
        g_cursor[i] = v;
    }
}
__global__ void fill_kernel(const int* __restrict__ src, const int* __restrict__ dst) {
    int i = blockIdx.x * blockDim.x + threadIdx.x;
    if (i >= RR * EE) return;
    int r = i / EE;
    int s = src[i], d = dst[i];
    int pos = atomicAdd(&g_cursor[r * NN + d], 1);
    float coef = g_so[r * NN + s] * g_si[r * NN + d];
    g_edge[pos] = make_int2(s, __float_as_int(coef));
}

// ================= precision splits =================
__global__ void split_x_kernel(const float* __restrict__ in,
                               __nv_bfloat16* __restrict__ hi,
                               __nv_bfloat16* __restrict__ lo, size_t n4) {
    size_t i = (size_t)blockIdx.x * blockDim.x + threadIdx.x;
    if (i >= n4) return;
    float4 v = ((const float4*)in)[i];
    float vv[4] = {v.x, v.y, v.z, v.w};
    __nv_bfloat16 h[4], l[4];
#pragma unroll
    for (int q = 0; q < 4; q++) {
        h[q] = __float2bfloat16_rn(vv[q]);
        l[q] = __float2bfloat16_rn(vv[q] - __bfloat162float(h[q]));
    }
    __nv_bfloat162 hh0; hh0.x = h[0]; hh0.y = h[1];
    __nv_bfloat162 hh1; hh1.x = h[2]; hh1.y = h[3];
    __nv_bfloat162 ll0; ll0.x = l[0]; ll0.y = l[1];
    __nv_bfloat162 ll1; ll1.x = l[2]; ll1.y = l[3];
    ((__nv_bfloat162*)hi)[i * 2]     = hh0;
    ((__nv_bfloat162*)hi)[i * 2 + 1] = hh1;
    ((__nv_bfloat162*)lo)[i * 2]     = ll0;
    ((__nv_bfloat162*)lo)[i * 2 + 1] = ll1;
}

__global__ void wsplit_kernel(const float* __restrict__ W,
                              __nv_bfloat16* __restrict__ thi,
                              __nv_bfloat16* __restrict__ tlo, int K) {
    int i = blockIdx.x * blockDim.x + threadIdx.x;
    if (i >= RR * K * DH) return;
    int r = i / (K * DH);
    int rem = i - r * K * DH;
    int k = rem / DH;
    int n = rem - k * DH;
    float v = W[i];
    __nv_bfloat16 h = __float2bfloat16_rn(v);
    __nv_bfloat16 l = __float2bfloat16_rn(v - __bfloat162float(h));
    size_t o = (size_t)r * DH * K + (size_t)n * K + k;
    thi[o] = h;
    tlo[o] = l;
}

// ================= mma.sync bf16 split GEMM (2 CTAs/SM), fp16 z output =================
__device__ __forceinline__ void load_stage(uint32_t sb, int st, int c, int K, int mbase,
                                           const __nv_bfloat16* __restrict__ Ahi,
                                           const __nv_bfloat16* __restrict__ Alo,
                                           const __nv_bfloat16* __restrict__ Bh,
                                           const __nv_bfloat16* __restrict__ Bl, int tid) {
    int k0 = c * KC;
    uint32_t sbase = sb + st * STAGE_B;
#pragma unroll
    for (int i = 0; i < 8; i++) {
        int idx = tid + i * 256;
        int tile = idx >> 9;
        int p = idx & 511;
        int row = p >> 2, seg = p & 3;
        uint32_t sa = sbase + tile * TILE_B + row * (ASTR * 2) + seg * 16;
        const __nv_bfloat16* gsrc;
        int sz = 16;
        if (tile < 2) {
            int grow = mbase + row;
            const __nv_bfloat16* base = (tile == 0) ? Ahi : Alo;
            gsrc = base + (size_t)grow * K + k0 + seg * 8;
            if (grow >= NN) sz = 0;
        } else {
            const __nv_bfloat16* base = (tile == 2) ? Bh : Bl;
            gsrc = base + (size_t)row * K + k0 + seg * 8;
        }
        asm volatile("cp.async.cg.shared.global [%0], [%1], 16, %2;"
                     :: "r"(sa), "l"(gsrc), "r"(sz));
    }
    asm volatile("cp.async.commit_group;" ::: "memory");
}

__global__ __launch_bounds__(256, 2)
void mma_gemm(int K,
              const __nv_bfloat16* __restrict__ Ahi, const __nv_bfloat16* __restrict__ Alo,
              const __nv_bfloat16* __restrict__ Bhi_all, const __nv_bfloat16* __restrict__ Blo_all,
              __half* __restrict__ Call) {
    extern __shared__ char smem[];
    uint32_t sb = smem_u32(smem);
    int tid = threadIdx.x, wid = tid >> 5, lane = tid & 31;
    int r = blockIdx.x;                  // fast dim: relation (A shared in L2)
    int mbase = blockIdx.y * 128;
    const __nv_bfloat16* Bh = Bhi_all + (size_t)r * DH * K;
    const __nv_bfloat16* Bl = Blo_all + (size_t)r * DH * K;
    __half* C = Call + (size_t)r * NN * DH;
    const int warp_m = (wid & 3) * 32;
    const int warp_n = (wid >> 2) * 64;

    float acc[2][8][4];
#pragma unroll
    for (int mt = 0; mt < 2; mt++)
#pragma unroll
        for (int nt = 0; nt < 8; nt++)
#pragma unroll
            for (int q = 0; q < 4; q++) acc[mt][nt][q] = 0.0f;

    const int nchunk = K / KC;
    load_stage(sb, 0, 0, K, mbase, Ahi, Alo, Bh, Bl, tid);

    for (int c = 0; c < nchunk; c++) {
        if (c + 1 < nchunk) {
            load_stage(sb, (c + 1) & 1, c + 1, K, mbase, Ahi, Alo, Bh, Bl, tid);
            asm volatile("cp.async.wait_group 1;" ::: "memory");
        } else {
            asm volatile("cp.async.wait_group 0;" ::: "memory");
        }
        __syncthreads();

        uint32_t base = sb + (c & 1) * STAGE_B;
#pragma unroll
        for (int ks = 0; ks < KC; ks += 16) {
            uint32_t ah[2][4], al[2][4];
            const int ar = lane & 15;
            const int ac = ks + ((lane >> 4) << 3);
#pragma unroll
            for (int mt = 0; mt < 2; mt++) {
                uint32_t addr = base + ((warp_m + mt * 16 + ar) * ASTR + ac) * 2;
                LDSM4(ah[mt], addr);
                LDSM4(al[mt], addr + TILE_B);
            }
            const int br = ((lane >> 4) << 3) + (lane & 7);
            const int bc = ks + (((lane >> 3) & 1) << 3);
#pragma unroll
            for (int j = 0; j < 4; j++) {
                uint32_t bh4[4], bl4[4];
                uint32_t addr = base + 2 * TILE_B + ((warp_n + j * 16 + br) * ASTR + bc) * 2;
                LDSM4(bh4, addr);
                LDSM4(bl4, addr + TILE_B);
#pragma unroll
                for (int mt = 0; mt < 2; mt++) {
#pragma unroll
                    for (int half = 0; half < 2; half++) {
                        float* a4 = acc[mt][j * 2 + half];
                        mma16816(a4, ah[mt], &bh4[half * 2]);
                        mma16816(a4, ah[mt], &bl4[half * 2]);
                        mma16816(a4, al[mt], &bh4[half * 2]);
                    }
                }
            }
        }
        __syncthreads();
    }

    // epilogue: fp32 acc -> fp16 z
#pragma unroll
    for (int mt = 0; mt < 2; mt++) {
        int row0 = mbase + warp_m + mt * 16 + (lane >> 2);
#pragma unroll
        for (int nt = 0; nt < 8; nt++) {
            int col = warp_n + nt * 8 + (lane & 3) * 2;
            if (row0 < NN)
                *(__half2*)(C + (size_t)row0 * DH + col) =
                    __floats2half2_rn(acc[mt][nt][0], acc[mt][nt][1]);
            if (row0 + 8 < NN)
                *(__half2*)(C + (size_t)(row0 + 8) * DH + col) =
                    __floats2half2_rn(acc[mt][nt][2], acc[mt][nt][3]);
        }
    }
}

// ================= gather: warp per dst node, fp16 z rows =================
template <int MODE>
__global__ __launch_bounds__(256)
void gather_kernel(const __half* __restrict__ z, const float* __restrict__ bias,
                   float* __restrict__ outf,
                   __nv_bfloat16* __restrict__ outhi, __nv_bfloat16* __restrict__ outlo) {
    int w = blockIdx.x * 8 + (threadIdx.x >> 5);
    if (w >= NN) return;
    int lane = threadIdx.x & 31;
    int c0 = lane * 4;

    float accT[4];
#pragma unroll
    for (int j = 0; j < 4; j++)
        accT[j] = bias[c0 + j] + bias[DH + c0 + j] + bias[2 * DH + c0 + j];

#pragma unroll
    for (int r = 0; r < RR; r++) {
        int idx = r * NN + w;
        int beg = g_off[idx];
        int end = g_off[idx + 1];
        const __half* zr = z + (size_t)r * NN * DH;
        int e = beg;
        for (; e + 2 <= end; e += 2) {
            int2 e0 = __ldg(&g_edge[e]);
            int2 e1 = __ldg(&g_edge[e + 1]);
            uint2 u0 = __ldg((const uint2*)(zr + (size_t)e0.x * DH + c0));
            uint2 u1 = __ldg((const uint2*)(zr + (size_t)e1.x * DH + c0));
            float c0f = __int_as_float(e0.y);
            float c1f = __int_as_float(e1.y);
            float2 a0 = __half22float2(*(__half2*)&u0.x);
            float2 b0 = __half22float2(*(__half2*)&u0.y);
            float2 a1 = __half22float2(*(__half2*)&u1.x);
            float2 b1 = __half22float2(*(__half2*)&u1.y);
            accT[0] = fmaf(c0f, a0.x, accT[0]);
            accT[1] = fmaf(c0f, a0.y, accT[1]);
            accT[2] = fmaf(c0f, b0.x, accT[2]);
            accT[3] = fmaf(c0f, b0.y, accT[3]);
            accT[0] = fmaf(c1f, a1.x, accT[0]);
            accT[1] = fmaf(c1f, a1.y, accT[1]);
            accT[2] = fmaf(c1f, b1.x, accT[2]);
            accT[3] = fmaf(c1f, b1.y, accT[3]);
        }
        if (e < end) {
            int2 e0 = __ldg(&g_edge[e]);
            uint2 u0 = __ldg((const uint2*)(zr + (size_t)e0.x * DH + c0));
            float c0f = __int_as_float(e0.y);
            float2 a0 = __half22float2(*(__half2*)&u0.x);
            float2 b0 = __half22float2(*(__half2*)&u0.y);
            accT[0] = fmaf(c0f, a0.x, accT[0]);
            accT[1] = fmaf(c0f, a0.y, accT[1]);
            accT[2] = fmaf(c0f, b0.x, accT[2]);
            accT[3] = fmaf(c0f, b0.y, accT[3]);
        }
    }

    if (MODE == 0) {
#pragma unroll
        for (int j = 0; j < 4; j++)
            accT[j] = (accT[j] > 0.f) ? accT[j] : NEG_SLOPE * accT[j];
        __nv_bfloat16 h[4], l[4];
#pragma unroll
        for (int j = 0; j < 4; j++) {
            h[j] = __float2bfloat16_rn(accT[j]);
            l[j] = __float2bfloat16_rn(accT[j] - __bfloat162float(h[j]));
        }
        __nv_bfloat162 hh0; hh0.x = h[0]; hh0.y = h[1];
        __nv_bfloat162 hh1; hh1.x = h[2]; hh1.y = h[3];
        __nv_bfloat162 ll0; ll0.x = l[0]; ll0.y = l[1];
        __nv_bfloat162 ll1; ll1.x = l[2]; ll1.y = l[3];
        __nv_bfloat162* oh = (__nv_bfloat162*)(outhi + (size_t)w * DH + c0);
        __nv_bfloat162* ol = (__nv_bfloat162*)(outlo + (size_t)w * DH + c0);
        oh[0] = hh0; oh[1] = hh1;
        ol[0] = ll0; ol[1] = ll1;
    } else {
        *(float4*)(outf + (size_t)w * DH + c0) = make_float4(accT[0], accT[1], accT[2], accT[3]);
    }
}

// ================= logits =================
__global__ __launch_bounds__(256)
void logits_kernel(const float* __restrict__ h2, const float* __restrict__ fcW,
                   const float* __restrict__ fcb, float* __restrict__ out) {
    __shared__ float Ws[DH * NCLS];
    __shared__ float bs[NCLS];
    int tid = threadIdx.x;
    for (int i = tid; i < DH * NCLS; i += 256) Ws[i] = fcW[i];
    if (tid < NCLS) bs[tid] = fcb[tid];
    __syncthreads();

    int n = blockIdx.x * 256 + tid;
    if (n >= NN) return;
    const float4* row = (const float4*)(h2 + (size_t)n * DH);
    float acc[NCLS];
#pragma unroll
    for (int c = 0; c < NCLS; c++) acc[c] = bs[c];
    for (int k4 = 0; k4 < DH / 4; k4++) {
        float4 hv = row[k4];
        float hs[4] = {hv.x, hv.y, hv.z, hv.w};
#pragma unroll
        for (int u = 0; u < 4; u++) {
            int k = k4 * 4 + u;
#pragma unroll
            for (int c = 0; c < NCLS; c++) acc[c] = fmaf(hs[u], Ws[k * NCLS + c], acc[c]);
        }
    }
    float* o = out + (size_t)n * NCLS;
#pragma unroll
    for (int c = 0; c < NCLS; c++) o[c] = acc[c];
}

// ================= launch =================
extern "C" void kernel_launch(void* const* d_in, const int* in_sizes, int n_in,
                              void* d_out, int out_size) {
    const float* x   = (const float*)d_in[0];
    const int*   src = (const int*)  d_in[1];
    const int*   dst = (const int*)  d_in[2];
    const float* W0  = (const float*)d_in[3];
    const float* b0  = (const float*)d_in[4];
    const float* W1  = (const float*)d_in[5];
    const float* b1  = (const float*)d_in[6];
    const float* fcW = (const float*)d_in[7];
    const float* fcb = (const float*)d_in[8];

    float* out    = (float*)d_out;
    float* h2     = out;
    float* logits = out + (size_t)NN * DH;

    const int T = 256;

    __half* zbuf;  cudaGetSymbolAddress((void**)&zbuf, g_z);
    __nv_bfloat16 *xhi, *xlo, *hhi, *hlo, *w0hi, *w0lo, *w1hi, *w1lo;
    cudaGetSymbolAddress((void**)&xhi, g_xhi);
    cudaGetSymbolAddress((void**)&xlo, g_xlo);
    cudaGetSymbolAddress((void**)&hhi, g_hhi);
    cudaGetSymbolAddress((void**)&hlo, g_hlo);
    cudaGetSymbolAddress((void**)&w0hi, g_w0hi);
    cudaGetSymbolAddress((void**)&w0lo, g_w0lo);
    cudaGetSymbolAddress((void**)&w1hi, g_w1hi);
    cudaGetSymbolAddress((void**)&w1lo, g_w1lo);

    cudaFuncSetAttribute(mma_gemm, cudaFuncAttributeMaxDynamicSharedMemorySize, GS_TOTAL);

    const int gemmBlocks = (NN + 127) / 128;
    const int gatherGrid = (NN + 7) / 8;

    // (0..2) splits, (3) layer-0 GEMM  -> ncu captures launch index 3
    size_t xn4 = (size_t)NN * DIN / 4;
    split_x_kernel<<<(int)((xn4 + T - 1) / T), T>>>(x, xhi, xlo, xn4);
    wsplit_kernel<<<(RR * DIN * DH + T - 1) / T, T>>>(W0, w0hi, w0lo, DIN);
    wsplit_kernel<<<(RR * DH * DH + T - 1) / T, T>>>(W1, w1hi, w1lo, DH);
    mma_gemm<<<dim3(RR, gemmBlocks), T, GS_TOTAL>>>(DIN, xhi, xlo, w0hi, w0lo, zbuf);

    // degrees + CSR
    deg_zero_kernel<<<(SCAN_N + T - 1) / T, T>>>();
    deg_hist_kernel<<<(RR * EE + T - 1) / T, T>>>(src, dst);
    deg_scale_kernel<<<(SCAN_N + T - 1) / T, T>>>();
    scan1_kernel<<<SCAN_NB, SCAN_B>>>();
    scan2_kernel<<<1, 32>>>();
    scan3_kernel<<<SCAN_NB, SCAN_B>>>();
    fill_kernel<<<(RR * EE + T - 1) / T, T>>>(src, dst);

    // layer 0 gather -> h (bf16 split)
    gather_kernel<0><<<gatherGrid, T>>>(zbuf, b0, nullptr, hhi, hlo);

    // layer 1
    mma_gemm<<<dim3(RR, gemmBlocks), T, GS_TOTAL>>>(DH, hhi, hlo, w1hi, w1lo, zbuf);
    gather_kernel<1><<<gatherGrid, T>>>(zbuf, b1, h2, nullptr, nullptr);

    // fc head
    logits_kernel<<<(NN + T - 1) / T, T>>>(h2, fcW, fcb, logits);
}